// round 1
// baseline (speedup 1.0000x reference)
#include <cuda_runtime.h>

#define DF   64
#define DC   256
#define HF   240
#define WF   320
#define LC   4800
#define WIN  5
#define WW   25
#define ITEMS 4
#define TPB  128
#define FSTRIDE 68   // padded smem row stride (floats): 16B-aligned, conflict-free LDS.128

__device__ float g_Wfused[DC * DF];
__device__ float g_biasf[DF];

// Wfused[i][j] = sum_k Wd[i][k] * Wm[64+k][j];  biasf[j] = bm[j] + sum_k bd[k]*Wm[64+k][j]
__global__ void fuse_weights_kernel(const float* __restrict__ Wd,
                                    const float* __restrict__ Wm,
                                    const float* __restrict__ bd,
                                    const float* __restrict__ bm) {
    int i = blockIdx.x;      // 0..255
    int j = threadIdx.x;     // 0..63
    float acc = 0.f;
#pragma unroll
    for (int k = 0; k < DF; k++)
        acc += Wd[i * DF + k] * Wm[(DF + k) * DF + j];
    g_Wfused[i * DF + j] = acc;
    if (i == 0) {
        float b = bm[j];
#pragma unroll
        for (int k = 0; k < DF; k++)
            b += bd[k] * Wm[(DF + k) * DF + j];
        g_biasf[j] = b;
    }
}

__global__ __launch_bounds__(TPB) void fine_main_kernel(
    const float* __restrict__ f0, const float* __restrict__ f1,
    const float* __restrict__ c0, const float* __restrict__ c1,
    const float* __restrict__ Wm,
    const int* __restrict__ b_ids, const int* __restrict__ cy,
    const int* __restrict__ cx, const int* __restrict__ ci,
    float* __restrict__ out, int N)
{
    __shared__ float s_WmT[DF * FSTRIDE];    // [j][k] transposed top half of Wm
    __shared__ float s_fwin[28 * FSTRIDE];   // [pos][ch], rows 25..27 are zero pad
    __shared__ float s_cc[DF];
    __shared__ float s_part[2][DF];

    const int tid = threadIdx.x;

    // Stage Wm_top transposed: s_WmT[j][k] = Wm[k][j]
    for (int idx = tid; idx < DF * DF; idx += TPB) {
        int k = idx >> 6, j = idx & 63;
        s_WmT[j * FSTRIDE + k] = Wm[k * DF + j];
    }
    // Zero the 3 pad rows of the window tile
    for (int idx = tid; idx < 3 * FSTRIDE; idx += TPB)
        s_fwin[25 * FSTRIDE + idx] = 0.f;

    const int w    = tid >> 5;     // warp id 0..3 -> position phase
    const int lane = tid & 31;
    const int j0 = lane, j1 = lane + 32;

    const int totalItems = 2 * N;

    for (int it = 0; it < ITEMS; ++it) {
        int item = blockIdx.x * ITEMS + it;
        if (item >= totalItems) break;
        int s = (item >= N) ? 1 : 0;
        int p = item - s * N;

        const float* fsrc = s ? f1 : f0;
        const float* csrc = s ? c1 : c0;
        int b = __ldg(b_ids + p);
        int y = __ldg(cy + p);
        int x = __ldg(cx + p);
        int c = __ldg(ci + p);

        const float* fbase = fsrc + (size_t)b * DF * (HF * WF)
                                  + (size_t)(y - 2) * WF + (x - 2);
        const float* cvec  = csrc + ((size_t)b * LC + c) * DC;

        __syncthreads();   // prev item fully consumed; WmT/pad ready on first iter

        // ---- gather 5x5x64 window (ch-major idx -> runs of 5 contiguous floats) ----
        for (int idx = tid; idx < WW * DF; idx += TPB) {
            int ch  = idx / WW;
            int pos = idx - ch * WW;
            int dy  = pos / WIN;
            int dx  = pos - dy * WIN;
            s_fwin[pos * FSTRIDE + ch] =
                __ldg(fbase + (size_t)ch * (HF * WF) + dy * WF + dx);
        }

        // ---- coarse projection: cc[j] = biasf[j] + sum_i cvec[i]*Wfused[i][j] ----
        {
            int g = tid >> 6;        // 0 or 1 (half of i-range)
            int j = tid & 63;
            float partial = 0.f;
            const float* wf = g_Wfused + (size_t)g * 128 * DF + j;
            const float* cv = cvec + g * 128;
#pragma unroll 8
            for (int i = 0; i < 128; i++)
                partial += __ldg(cv + i) * wf[(size_t)i * DF];
            s_part[g][j] = partial;
        }
        __syncthreads();
        if (tid < DF)
            s_cc[tid] = s_part[0][tid] + s_part[1][tid] + g_biasf[tid];
        __syncthreads();

        // ---- GEMM: out[pos][j] = sum_k fwin[pos][k] * WmT[j][k] + cc[j] ----
        float acc0[7], acc1[7];
#pragma unroll
        for (int a = 0; a < 7; a++) { acc0[a] = 0.f; acc1[a] = 0.f; }

        const float4* wr0 = reinterpret_cast<const float4*>(s_WmT + j0 * FSTRIDE);
        const float4* wr1 = reinterpret_cast<const float4*>(s_WmT + j1 * FSTRIDE);
#pragma unroll
        for (int k4 = 0; k4 < 16; k4++) {
            float4 w0 = wr0[k4];
            float4 w1 = wr1[k4];
#pragma unroll
            for (int a = 0; a < 7; a++) {
                const float4 fv = *reinterpret_cast<const float4*>(
                    s_fwin + (w + a * 4) * FSTRIDE + k4 * 4);
                acc0[a] += fv.x * w0.x + fv.y * w0.y + fv.z * w0.z + fv.w * w0.w;
                acc1[a] += fv.x * w1.x + fv.y * w1.y + fv.z * w1.z + fv.w * w1.w;
            }
        }

        float cc0 = s_cc[j0], cc1 = s_cc[j1];
        size_t obase = ((size_t)s * N + p) * (size_t)(WW * DF);
#pragma unroll
        for (int a = 0; a < 7; a++) {
            int pos = w + a * 4;
            if (pos < WW) {
                out[obase + pos * DF + j0] = acc0[a] + cc0;
                out[obase + pos * DF + j1] = acc1[a] + cc1;
            }
        }
    }
}

extern "C" void kernel_launch(void* const* d_in, const int* in_sizes, int n_in,
                              void* d_out, int out_size) {
    const float* f0    = (const float*)d_in[0];
    const float* f1    = (const float*)d_in[1];
    const float* c0    = (const float*)d_in[2];
    const float* c1    = (const float*)d_in[3];
    const float* Wd    = (const float*)d_in[4];
    const float* bd    = (const float*)d_in[5];
    const float* Wm    = (const float*)d_in[6];
    const float* bm    = (const float*)d_in[7];
    const int*   b_ids = (const int*)d_in[8];
    const int*   cy    = (const int*)d_in[9];
    const int*   cx    = (const int*)d_in[10];
    const int*   ci    = (const int*)d_in[11];
    float* out = (float*)d_out;

    int N = in_sizes[8];   // 16384

    fuse_weights_kernel<<<DC, DF>>>(Wd, Wm, bd, bm);

    int totalItems = 2 * N;
    int blocks = (totalItems + ITEMS - 1) / ITEMS;
    fine_main_kernel<<<blocks, TPB>>>(f0, f1, c0, c1, Wm,
                                      b_ids, cy, cx, ci, out, N);
}

// round 2
// speedup vs baseline: 1.1142x; 1.1142x over previous
#include <cuda_runtime.h>

#define DF   64
#define DC   256
#define HF   240
#define WF   320
#define HW   (HF*WF)
#define LC   4800
#define WW   25
#define NMAX 16384

typedef unsigned long long u64;

__device__ float g_Wfused[DC * DF];
__device__ float g_biasf[DF];
__device__ float g_cc[2 * NMAX * DF];

// ---------------- packed f32x2 helpers ----------------
__device__ __forceinline__ u64 ffma2(u64 a, u64 b, u64 c) {
    u64 d;
    asm("fma.rn.f32x2 %0, %1, %2, %3;" : "=l"(d) : "l"(a), "l"(b), "l"(c));
    return d;
}
__device__ __forceinline__ u64 dup2(float x) {
    u64 d;
    asm("mov.b64 %0, {%1, %1};" : "=l"(d) : "f"(x));
    return d;
}
__device__ __forceinline__ float2 up2(u64 v) {
    float2 r;
    asm("mov.b64 {%0, %1}, %2;" : "=f"(r.x), "=f"(r.y) : "l"(v));
    return r;
}

// ---------------- weight fusion ----------------
// Wfused[i][j] = sum_k Wd[i][k] * Wm[64+k][j];  biasf[j] = bm[j] + sum_k bd[k]*Wm[64+k][j]
__global__ void fuse_weights_kernel(const float* __restrict__ Wd,
                                    const float* __restrict__ Wm,
                                    const float* __restrict__ bd,
                                    const float* __restrict__ bm) {
    int i = blockIdx.x;      // 0..255
    int j = threadIdx.x;     // 0..63
    float acc = 0.f;
#pragma unroll
    for (int k = 0; k < DF; k++)
        acc += Wd[i * DF + k] * Wm[(DF + k) * DF + j];
    g_Wfused[i * DF + j] = acc;
    if (i == 0) {
        float b = bm[j];
#pragma unroll
        for (int k = 0; k < DF; k++)
            b += bd[k] * Wm[(DF + k) * DF + j];
        g_biasf[j] = b;
    }
}

// ---------------- coarse projection: cc[item][64] = cvec[item] @ Wfused + biasf ----------------
#define CB_ITEMS 32
#define CV_STR   258   // smem stride: item*2 mod 32 -> conflict-free broadcasts

__global__ __launch_bounds__(128) void coarse_kernel(
    const float* __restrict__ c0, const float* __restrict__ c1,
    const int* __restrict__ b_ids, const int* __restrict__ ci,
    int N)
{
    __shared__ float s_cv[CB_ITEMS * CV_STR];
    __shared__ int   s_off[CB_ITEMS];
    __shared__ int   s_s[CB_ITEMS];

    int tid  = threadIdx.x;
    int base = blockIdx.x * CB_ITEMS;
    int total = 2 * N;

    if (tid < CB_ITEMS) {
        int item = base + tid;
        int s = 0, off = 0;
        if (item < total) {
            s = item >= N;
            int p = item - s * N;
            off = (__ldg(b_ids + p) * LC + __ldg(ci + p)) * DC;
        }
        s_s[tid]   = s;
        s_off[tid] = off;
    }
    __syncthreads();

    // stage 32 coarse vectors (coalesced per row)
    for (int idx = tid; idx < CB_ITEMS * DC; idx += 128) {
        int it = idx >> 8, k = idx & 255;
        const float* src = s_s[it] ? c1 : c0;
        s_cv[it * CV_STR + k] = __ldg(src + s_off[it] + k);
    }
    __syncthreads();

    int ig  = tid >> 4;   // 0..7, each handles 4 items
    int cgp = tid & 15;   // 4 columns each

    u64 acc[4][2];
#pragma unroll
    for (int m = 0; m < 4; m++) { acc[m][0] = 0ull; acc[m][1] = 0ull; }

    const float* cv0 = s_cv + (4 * ig) * CV_STR;

#pragma unroll 4
    for (int k = 0; k < DC; k++) {
        const u64* wq = (const u64*)(g_Wfused + k * DF + cgp * 4);
        u64 w0 = wq[0], w1 = wq[1];
#pragma unroll
        for (int m = 0; m < 4; m++) {
            u64 a = dup2(cv0[m * CV_STR + k]);
            acc[m][0] = ffma2(a, w0, acc[m][0]);
            acc[m][1] = ffma2(a, w1, acc[m][1]);
        }
    }

    float b0 = g_biasf[cgp * 4 + 0];
    float b1 = g_biasf[cgp * 4 + 1];
    float b2 = g_biasf[cgp * 4 + 2];
    float b3 = g_biasf[cgp * 4 + 3];

#pragma unroll
    for (int m = 0; m < 4; m++) {
        int item = base + 4 * ig + m;
        if (item < total) {
            float2 x0 = up2(acc[m][0]), x1 = up2(acc[m][1]);
            float4 o = make_float4(x0.x + b0, x0.y + b1, x1.x + b2, x1.y + b3);
            *(float4*)(g_cc + (size_t)item * DF + cgp * 4) = o;
        }
    }
}

// ---------------- main kernel: one warp per item ----------------
#define FSTR  28          // fwinT row stride (floats), 16B-aligned quads
#define ITEMF (DF * FSTR) // 1792 floats per item tile

__global__ __launch_bounds__(128) void fine_main_kernel(
    const float* __restrict__ f0, const float* __restrict__ f1,
    const float* __restrict__ Wm,
    const int* __restrict__ b_ids, const int* __restrict__ cy,
    const int* __restrict__ cx,
    float* __restrict__ out, int N)
{
    __shared__ __align__(16) float s_W[DF * DF];        // Wm top half, k-major
    __shared__ __align__(16) float s_f[4 * ITEMF + 8];  // 4 per-warp window tiles [k][pos]

    const int tid = threadIdx.x;

    // stage Wm[0:64][0:64] (already k-major, contiguous)
    {
        const float4* wsrc = (const float4*)Wm;
        float4* wdst = (float4*)s_W;
        for (int i = tid; i < DF * DF / 4; i += 128)
            wdst[i] = wsrc[i];
    }
    __syncthreads();

    const int wid  = tid >> 5;
    const int lane = tid & 31;

    int item = blockIdx.x * 4 + wid;
    if (item >= 2 * N) return;
    int s = item >= N;
    int p = item - s * N;

    const float* fsrc = s ? f1 : f0;
    int b = __ldg(b_ids + p);
    int y = __ldg(cy + p);
    int x = __ldg(cx + p);
    const float* fbase = fsrc + (size_t)b * (DF * HW) + (size_t)(y - 2) * WF + (x - 2);

    // gather 5x5x64 window into [k][pos] tile (per-warp)
    float* sw = s_f + wid * ITEMF;
    for (int idx = lane; idx < WW * DF; idx += 32) {
        int ch  = idx / WW;
        int pos = idx - ch * WW;
        int dy  = pos / 5;
        int dx  = pos - dy * 5;
        sw[ch * FSTR + pos] = __ldg(fbase + ch * HW + dy * WF + dx);
    }
    __syncwarp();

    const int pg = lane >> 3;  // posgroup: positions 8*pg .. 8*pg+7
    const int cg = lane & 7;   // colgroup: columns  8*cg .. 8*cg+7

    // prefetch coarse contribution (hidden behind GEMM)
    const float* ccp = g_cc + (size_t)item * DF + cg * 8;
    float4 ccA = __ldg((const float4*)ccp);
    float4 ccB = __ldg((const float4*)(ccp + 4));

    u64 acc[8][4];
#pragma unroll
    for (int q = 0; q < 8; q++)
#pragma unroll
        for (int r = 0; r < 4; r++) acc[q][r] = 0ull;

    const float* fp = sw  + pg * 8;
    const float* wp = s_W + cg * 8;

#pragma unroll 2
    for (int k = 0; k < DF; k++) {
        float4 fa = *(const float4*)(fp + k * FSTR);
        float4 fb = *(const float4*)(fp + k * FSTR + 4);
        u64 w0 = *(const u64*)(wp + k * DF + 0);
        u64 w1 = *(const u64*)(wp + k * DF + 2);
        u64 w2 = *(const u64*)(wp + k * DF + 4);
        u64 w3 = *(const u64*)(wp + k * DF + 6);
        u64 fd[8];
        fd[0] = dup2(fa.x); fd[1] = dup2(fa.y); fd[2] = dup2(fa.z); fd[3] = dup2(fa.w);
        fd[4] = dup2(fb.x); fd[5] = dup2(fb.y); fd[6] = dup2(fb.z); fd[7] = dup2(fb.w);
#pragma unroll
        for (int q = 0; q < 8; q++) {
            acc[q][0] = ffma2(fd[q], w0, acc[q][0]);
            acc[q][1] = ffma2(fd[q], w1, acc[q][1]);
            acc[q][2] = ffma2(fd[q], w2, acc[q][2]);
            acc[q][3] = ffma2(fd[q], w3, acc[q][3]);
        }
    }

    float* ob = out + (size_t)item * (WW * DF) + cg * 8;
#pragma unroll
    for (int q = 0; q < 8; q++) {
        int pos = pg * 8 + q;
        if (pos < WW) {
            float2 a0 = up2(acc[q][0]);
            float2 a1 = up2(acc[q][1]);
            float2 a2 = up2(acc[q][2]);
            float2 a3 = up2(acc[q][3]);
            float4 o0 = make_float4(a0.x + ccA.x, a0.y + ccA.y, a1.x + ccA.z, a1.y + ccA.w);
            float4 o1 = make_float4(a2.x + ccB.x, a2.y + ccB.y, a3.x + ccB.z, a3.y + ccB.w);
            *(float4*)(ob + pos * DF)     = o0;
            *(float4*)(ob + pos * DF + 4) = o1;
        }
    }
}

extern "C" void kernel_launch(void* const* d_in, const int* in_sizes, int n_in,
                              void* d_out, int out_size) {
    const float* f0    = (const float*)d_in[0];
    const float* f1    = (const float*)d_in[1];
    const float* c0    = (const float*)d_in[2];
    const float* c1    = (const float*)d_in[3];
    const float* Wd    = (const float*)d_in[4];
    const float* bd    = (const float*)d_in[5];
    const float* Wm    = (const float*)d_in[6];
    const float* bm    = (const float*)d_in[7];
    const int*   b_ids = (const int*)d_in[8];
    const int*   cy    = (const int*)d_in[9];
    const int*   cx    = (const int*)d_in[10];
    const int*   ci    = (const int*)d_in[11];
    float* out = (float*)d_out;

    int N = in_sizes[8];   // 16384
    int total = 2 * N;

    fuse_weights_kernel<<<DC, DF>>>(Wd, Wm, bd, bm);

    int cblocks = (total + CB_ITEMS - 1) / CB_ITEMS;
    coarse_kernel<<<cblocks, 128>>>(c0, c1, b_ids, ci, N);

    int mblocks = (total + 3) / 4;
    fine_main_kernel<<<mblocks, 128>>>(f0, f1, Wm, b_ids, cy, cx, out, N);
}